// round 1
// baseline (speedup 1.0000x reference)
#include <cuda_runtime.h>

#define SSIM_C1 1e-4f
#define SSIM_C2 9e-4f

// tile geometry
#define TW 64            // output tile width
#define TH 16            // output tile height
#define HW 74            // halo tile width  (TW + 10)
#define HH 26            // halo tile height (TH + 10)
#define SSTR 76          // smem row stride (even -> 8B-aligned float2 pairs)
#define NPAIR 37         // HW/2 column pairs
#define NBLOCKS (16*16*64)

typedef unsigned long long u64;

__device__ float g_partial[NBLOCKS];

__device__ __forceinline__ u64 pack2(float lo, float hi) {
    u64 r;
    asm("mov.b64 %0, {%1,%2};" : "=l"(r) : "f"(lo), "f"(hi));
    return r;
}
__device__ __forceinline__ void unpack2(u64 v, float& lo, float& hi) {
    asm("mov.b64 {%0,%1}, %2;" : "=f"(lo), "=f"(hi) : "l"(v));
}
__device__ __forceinline__ u64 fma2(u64 a, u64 b, u64 c) {
    u64 d;
    asm("fma.rn.f32x2 %0, %1, %2, %3;" : "=l"(d) : "l"(a), "l"(b), "l"(c));
    return d;
}
__device__ __forceinline__ u64 mul2(u64 a, u64 b) {
    u64 d;
    asm("mul.rn.f32x2 %0, %1, %2;" : "=l"(d) : "l"(a), "l"(b));
    return d;
}

__global__ __launch_bounds__(256) void ssim_main(
    const float* __restrict__ img1,
    const float* __restrict__ img2,
    const float* __restrict__ kw)
{
    __shared__ __align__(16) float s1[HH * SSTR];
    __shared__ __align__(16) float s2[HH * SSTR];
    __shared__ __align__(16) float vbuf[5 * TH * SSTR];   // 5 vertical-conv planes
    __shared__ float s_w[11];
    __shared__ float warpSums[8];

    const int tid = threadIdx.x;
    const int bx = blockIdx.x, by = blockIdx.y, bz = blockIdx.z;
    const int row0 = by * TH;
    const int col0 = bx * TW;

    // Recover 1D gaussian from 2D kernel: g[i] = row-sum (since sum(g)=1)
    if (tid < 11) {
        float s = 0.f;
        #pragma unroll
        for (int j = 0; j < 11; j++) s += kw[tid * 11 + j];
        s_w[tid] = s;
    }

    // ---- load halo tiles (zero padding outside image) ----
    const float* base1 = img1 + (size_t)bz * 1048576u;
    const float* base2 = img2 + (size_t)bz * 1048576u;
    for (int i = tid; i < HH * HW; i += 256) {
        int rr = i / HW;
        int cc = i - rr * HW;
        int gr = row0 - 5 + rr;
        int gc = col0 - 5 + cc;
        bool ok = ((unsigned)gr < 1024u) && ((unsigned)gc < 1024u);
        int gi = gr * 1024 + gc;
        float a = ok ? base1[gi] : 0.f;
        float b = ok ? base2[gi] : 0.f;
        s1[rr * SSTR + cc] = a;
        s2[rr * SSTR + cc] = b;
    }
    __syncthreads();

    // packed weights (both lanes identical)
    u64 w2[11];
    #pragma unroll
    for (int i = 0; i < 11; i++) w2[i] = pack2(s_w[i], s_w[i]);

    // ---- vertical pass: 5 planes, f32x2 over column pairs ----
    for (int t = tid; t < NPAIR * TH; t += 256) {
        int r = t / NPAIR;
        int p = t - r * NPAIR;
        u64 a0 = 0, a1 = 0, a2 = 0, a3 = 0, a4 = 0;
        const float* s1p = &s1[r * SSTR + 2 * p];
        const float* s2p = &s2[r * SSTR + 2 * p];
        #pragma unroll
        for (int i = 0; i < 11; i++) {
            float2 xv = *(const float2*)(s1p + i * SSTR);
            float2 yv = *(const float2*)(s2p + i * SSTR);
            u64 xa = pack2(xv.x, xv.y);
            u64 yb = pack2(yv.x, yv.y);
            a0 = fma2(w2[i], xa, a0);
            a1 = fma2(w2[i], yb, a1);
            a2 = fma2(w2[i], mul2(xa, xa), a2);
            a3 = fma2(w2[i], mul2(yb, yb), a3);
            a4 = fma2(w2[i], mul2(xa, yb), a4);
        }
        int off = r * SSTR + 2 * p;
        *(u64*)&vbuf[0 * TH * SSTR + off] = a0;
        *(u64*)&vbuf[1 * TH * SSTR + off] = a1;
        *(u64*)&vbuf[2 * TH * SSTR + off] = a2;
        *(u64*)&vbuf[3 * TH * SSTR + off] = a3;
        *(u64*)&vbuf[4 * TH * SSTR + off] = a4;
    }
    __syncthreads();

    // ---- horizontal pass + SSIM: each thread does 4 consecutive columns of one row ----
    const int hr  = tid >> 4;          // 0..15
    const int cl0 = (tid & 15) * 4;    // 0..60

    u64 res[5][2];
    #pragma unroll
    for (int q = 0; q < 5; q++) {
        const float* vp = &vbuf[q * TH * SSTR + hr * SSTR + cl0];
        float tv[14];
        #pragma unroll
        for (int j = 0; j < 14; j++) tv[j] = vp[j];
        u64 pk[13];
        #pragma unroll
        for (int j = 0; j < 13; j++) pk[j] = pack2(tv[j], tv[j + 1]);
        u64 a0 = 0, a1 = 0;
        #pragma unroll
        for (int j = 0; j < 11; j++) {
            a0 = fma2(w2[j], pk[j],     a0);
            a1 = fma2(w2[j], pk[j + 2], a1);
        }
        res[q][0] = a0;
        res[q][1] = a1;
    }

    float m1[4], m2[4], exx[4], eyy[4], exy[4];
    unpack2(res[0][0], m1[0], m1[1]);  unpack2(res[0][1], m1[2], m1[3]);
    unpack2(res[1][0], m2[0], m2[1]);  unpack2(res[1][1], m2[2], m2[3]);
    unpack2(res[2][0], exx[0], exx[1]); unpack2(res[2][1], exx[2], exx[3]);
    unpack2(res[3][0], eyy[0], eyy[1]); unpack2(res[3][1], eyy[2], eyy[3]);
    unpack2(res[4][0], exy[0], exy[1]); unpack2(res[4][1], exy[2], exy[3]);

    float ssum = 0.f;
    #pragma unroll
    for (int k = 0; k < 4; k++) {
        float a = m1[k], b = m2[k];
        float a2v = a * a, b2v = b * b, ab = a * b;
        float sx2 = exx[k] - a2v;
        float sy2 = eyy[k] - b2v;
        float sxy = exy[k] - ab;
        float num = (2.f * ab  + SSIM_C1) * (2.f * sxy + SSIM_C2);
        float den = (a2v + b2v + SSIM_C1) * (sx2 + sy2 + SSIM_C2);
        ssum += __fdividef(num, den);
    }

    // ---- block reduction (deterministic, no atomics) ----
    #pragma unroll
    for (int o = 16; o > 0; o >>= 1)
        ssum += __shfl_down_sync(0xffffffffu, ssum, o);
    const int wid = tid >> 5, lane = tid & 31;
    if (lane == 0) warpSums[wid] = ssum;
    __syncthreads();
    if (tid == 0) {
        float tot = 0.f;
        #pragma unroll
        for (int i = 0; i < 8; i++) tot += warpSums[i];
        int bid = bx + 16 * (by + 64 * bz);
        g_partial[bid] = tot;
    }
}

__global__ void ssim_finish(float* __restrict__ out)
{
    __shared__ double red[256];
    const int tid = threadIdx.x;
    double s = 0.0;
    for (int i = tid; i < NBLOCKS; i += 256) s += (double)g_partial[i];
    red[tid] = s;
    __syncthreads();
    #pragma unroll
    for (int o = 128; o > 0; o >>= 1) {
        if (tid < o) red[tid] += red[tid + o];
        __syncthreads();
    }
    if (tid == 0) out[0] = (float)(red[0] / 16777216.0);
}

extern "C" void kernel_launch(void* const* d_in, const int* in_sizes, int n_in,
                              void* d_out, int out_size)
{
    const float* img1 = (const float*)d_in[0];
    const float* img2 = (const float*)d_in[1];
    const float* kw   = (const float*)d_in[2];
    float* out = (float*)d_out;

    dim3 grid(16, 64, 16);   // 1024/64 x-tiles, 1024/16 y-tiles, 16 batch
    ssim_main<<<grid, 256>>>(img1, img2, kw);
    ssim_finish<<<1, 256>>>(out);
}